// round 3
// baseline (speedup 1.0000x reference)
#include <cuda_runtime.h>
#include <cstdint>

// Problem constants
#define N_TOT 32768     // 8*64*64 query vectors
#define K_TOT 8192      // codebook size
#define DDIM  64        // embedding dim
#define TN    64        // queries per CTA
#define TK    128       // codes per smem chunk
#define NCHUNK (K_TOT / TK)   // 64
#define ZQ_ELEMS 2097152      // 8*64*64*64

typedef unsigned long long ull;

// Scratch (no cudaMalloc allowed)
__device__ float g_enorm[K_TOT];
__device__ int   g_idx[N_TOT];
__device__ float g_partial[128];

__device__ __forceinline__ void fma_x2(ull& acc, ull a, ull b) {
    asm("fma.rn.f32x2 %0, %1, %2, %0;" : "+l"(acc) : "l"(a), "l"(b));
}
__device__ __forceinline__ ull dup_f32(float x) {
    ull r; unsigned int bits = __float_as_uint(x);
    asm("mov.b64 %0, {%1, %1};" : "=l"(r) : "r"(bits));
    return r;
}
__device__ __forceinline__ void unpack_x2(ull v, float& lo, float& hi) {
    unsigned int l, h;
    asm("mov.b64 {%0, %1}, %2;" : "=r"(l), "=r"(h) : "l"(v));
    lo = __uint_as_float(l); hi = __uint_as_float(h);
}

// ---------------------------------------------------------------------------
// Kernel 0: ||e_k||^2  — strict sequential fl(acc + fl(e*e)) chain,
// emulating jnp.sum(embedding**2, axis=1) (square rounded, then added; no fma)
// ---------------------------------------------------------------------------
__global__ void prep_kernel(const float* __restrict__ emb) {
    int k = blockIdx.x * blockDim.x + threadIdx.x;
    if (k < K_TOT) {
        const float* r = emb + (size_t)k * DDIM;
        float s = 0.f;
        #pragma unroll
        for (int c = 0; c < DDIM; ++c)
            s = __fadd_rn(s, __fmul_rn(r[c], r[c]));
        g_enorm[k] = s;
    }
}

// ---------------------------------------------------------------------------
// Kernel 1: fused exact-fp32 distance + argmin, emulating the reference's
// fp32 rounding:  d = fl( fl(znorm_n + enorm_k) - fl(2*dot_nk) )
//   znorm: sequential fl(acc + fl(z*z)) over c = 0..63
//   dot:   sequential fma.rn chain over c = 0..63 (Eigen gebp order)
// argmin ties -> lowest index (jnp.argmin semantics)
// ---------------------------------------------------------------------------
__global__ __launch_bounds__(256) void argmin_kernel(
    const float* __restrict__ z, const float* __restrict__ emb)
{
    __shared__ float zs[DDIM * TN];   // [d][n]  16KB, exact fp32
    __shared__ float es[TK * DDIM];   // [k][d]  32KB  (reused for reduction)
    __shared__ float zn[TN];          // ||z_n||^2, reference rounding

    const int tid = threadIdx.x;
    const int n0  = blockIdx.x * TN;
    // z layout: idx = b*262144 + c*4096 + (n & 4095),  n = b*4096 + hw
    const int zbase = (n0 >> 12) * 262144 + (n0 & 4095);

    // stage z tile, transposed to [d][n]
    for (int r = tid; r < DDIM * TN; r += 256)
        zs[r] = z[zbase + (r >> 6) * 4096 + (r & 63)];
    __syncthreads();

    // per-row znorm, strict sequential order c = 0..63
    if (tid < TN) {
        float s = 0.f;
        #pragma unroll
        for (int c = 0; c < DDIM; ++c) {
            float v = zs[c * TN + tid];
            s = __fadd_rn(s, __fmul_rn(v, v));
        }
        zn[tid] = s;
    }

    const int tg = tid & 15;
    const int kg = tid >> 4;

    // this thread's 4 row norms: n-locals {2tg, 2tg+1, 2tg+32, 2tg+33}
    __syncthreads();
    float zn0, zn1, zn2, zn3;
    zn0 = zn[2 * tg];      zn1 = zn[2 * tg + 1];
    zn2 = zn[2 * tg + 32]; zn3 = zn[2 * tg + 33];

    float minv[4] = {1e30f, 1e30f, 1e30f, 1e30f};
    int   mini[4] = {0, 0, 0, 0};

    for (int chunk = 0; chunk < NCHUNK; ++chunk) {
        __syncthreads();
        // stage 128 codes (k-major, contiguous copy), exact fp32
        {
            const float4* src = (const float4*)(emb + (size_t)chunk * TK * DDIM);
            float4* dst = (float4*)es;
            #pragma unroll
            for (int r = 0; r < (TK * DDIM / 4) / 256; ++r)
                dst[tid + r * 256] = src[tid + r * 256];
        }
        __syncthreads();

        ull acc[2][8];
        #pragma unroll
        for (int p = 0; p < 2; ++p)
            #pragma unroll
            for (int j = 0; j < 8; ++j) acc[p][j] = 0ull;

        // strict sequential-in-d fma chains (matches Eigen's k-ordered fma)
        #pragma unroll 4
        for (int d = 0; d < DDIM; ++d) {
            ull z0 = *(const ull*)&zs[d * TN + 2 * tg];
            ull z1 = *(const ull*)&zs[d * TN + 2 * tg + 32];
            #pragma unroll
            for (int j = 0; j < 8; ++j) {
                ull ep = dup_f32(es[(kg + 16 * j) * DDIM + d]);
                fma_x2(acc[0][j], z0, ep);
                fma_x2(acc[1][j], z1, ep);
            }
        }

        const int kbase = chunk * TK + kg;
        #pragma unroll
        for (int j = 0; j < 8; ++j) {
            int k = kbase + 16 * j;
            float en = g_enorm[k];
            float lo, hi;
            // p = 0 : rows 2tg, 2tg+1
            unpack_x2(acc[0][j], lo, hi);
            {
                float s0 = __fsub_rn(__fadd_rn(zn0, en), __fmul_rn(2.f, lo));
                float s1 = __fsub_rn(__fadd_rn(zn1, en), __fmul_rn(2.f, hi));
                if (s0 < minv[0]) { minv[0] = s0; mini[0] = k; }
                if (s1 < minv[1]) { minv[1] = s1; mini[1] = k; }
            }
            // p = 1 : rows 2tg+32, 2tg+33
            unpack_x2(acc[1][j], lo, hi);
            {
                float s0 = __fsub_rn(__fadd_rn(zn2, en), __fmul_rn(2.f, lo));
                float s1 = __fsub_rn(__fadd_rn(zn3, en), __fmul_rn(2.f, hi));
                if (s0 < minv[2]) { minv[2] = s0; mini[2] = k; }
                if (s1 < minv[3]) { minv[3] = s1; mini[3] = k; }
            }
        }
    }

    // cross-(k-group) reduction: 16 partial results per n, lowest-index ties
    __syncthreads();
    float* rv = es;                       // [TN][16] floats
    int*   ri = (int*)(es + TN * 16);     // [TN][16] ints
    #pragma unroll
    for (int p = 0; p < 2; ++p)
        #pragma unroll
        for (int q = 0; q < 2; ++q) {
            int nl = 2 * tg + 32 * p + q;
            rv[nl * 16 + kg] = minv[2 * p + q];
            ri[nl * 16 + kg] = mini[2 * p + q];
        }
    __syncthreads();
    if (tid < TN) {
        float bv = rv[tid * 16];
        int   bi = ri[tid * 16];
        #pragma unroll
        for (int g = 1; g < 16; ++g) {
            float v = rv[tid * 16 + g];
            int   i = ri[tid * 16 + g];
            if (v < bv || (v == bv && i < bi)) { bv = v; bi = i; }
        }
        g_idx[n0 + tid] = bi;
    }
}

// ---------------------------------------------------------------------------
// Kernel 2: straight-through z_q = fl(z + fl(zq - z)) (reference's exact two
// fp32 ops), loss partials from fl(zq - z), index writeout
// ---------------------------------------------------------------------------
__global__ __launch_bounds__(256) void gather_kernel(
    const float* __restrict__ z, const float* __restrict__ emb,
    float* __restrict__ out, int out_size)
{
    const int n = blockIdx.x * 256 + threadIdx.x;
    const int idx = g_idx[n];
    const int obase = (n >> 12) * 262144 + (n & 4095);

    const float4* er = (const float4*)(emb + (size_t)idx * DDIM);
    float acc = 0.f;
    #pragma unroll
    for (int i = 0; i < DDIM / 4; ++i) {
        float4 e4 = er[i];
        float ev[4] = {e4.x, e4.y, e4.z, e4.w};
        #pragma unroll
        for (int c = 0; c < 4; ++c) {
            int d = 4 * i + c;
            float zv = z[obase + d * 4096];
            float df = __fsub_rn(ev[c], zv);           // fl(zq - z)
            out[obase + d * 4096] = __fadd_rn(zv, df); // fl(z + fl(zq - z))
            acc = fmaf(df, df, acc);
        }
    }

    if (out_size >= ZQ_ELEMS + 1 + N_TOT)
        out[ZQ_ELEMS + 1 + n] = (float)idx;

    // deterministic block reduction
    __shared__ float red[256];
    red[threadIdx.x] = acc;
    __syncthreads();
    #pragma unroll
    for (int s = 128; s > 0; s >>= 1) {
        if (threadIdx.x < s) red[threadIdx.x] += red[threadIdx.x + s];
        __syncthreads();
    }
    if (threadIdx.x == 0) g_partial[blockIdx.x] = red[0];
}

__global__ void loss_kernel(float* __restrict__ out, int out_size) {
    __shared__ float red[128];
    red[threadIdx.x] = g_partial[threadIdx.x];
    __syncthreads();
    #pragma unroll
    for (int s = 64; s > 0; s >>= 1) {
        if (threadIdx.x < s) red[threadIdx.x] += red[threadIdx.x + s];
        __syncthreads();
    }
    if (threadIdx.x == 0 && out_size >= ZQ_ELEMS + 1) {
        // loss = mean + beta*mean, rounded like fl(m + fl(0.25*m))
        float m = red[0] / (float)ZQ_ELEMS;
        out[ZQ_ELEMS] = __fadd_rn(m, __fmul_rn(0.25f, m));
    }
}

// ---------------------------------------------------------------------------
extern "C" void kernel_launch(void* const* d_in, const int* in_sizes, int n_in,
                              void* d_out, int out_size) {
    const float* z   = (const float*)d_in[0];
    const float* emb = (const float*)d_in[1];
    float* out = (float*)d_out;

    prep_kernel<<<K_TOT / 256, 256>>>(emb);
    argmin_kernel<<<N_TOT / TN, 256>>>(z, emb);
    gather_kernel<<<N_TOT / 256, 256>>>(z, emb, out, out_size);
    loss_kernel<<<1, 128>>>(out, out_size);
}

// round 4
// speedup vs baseline: 1.0933x; 1.0933x over previous
#include <cuda_runtime.h>
#include <cstdint>

#define N_TOT 32768
#define K_TOT 8192
#define DDIM  64
#define ZQ_ELEMS 2097152
#define CHUNK_K 64
#define NCHUNKS (K_TOT / CHUNK_K)      // 128
#define KSPLIT 4
#define CHUNKS_PER_CTA (NCHUNKS / KSPLIT)  // 32
#define M_CTA 128
#define EPS 3e-4f

typedef unsigned long long ull;

// device scratch (no cudaMalloc allowed)
__device__ float g_enorm[K_TOT];
__device__ float g_znorm[N_TOT];
__device__ float g_chunkmin[N_TOT * NCHUNKS];   // 16MB
__device__ float g_rowmin[N_TOT];
__device__ ull   g_win[N_TOT];
__device__ float g_partial[128];

__device__ __forceinline__ unsigned tf32u(float x) {
    unsigned u;
    asm("cvt.rna.tf32.f32 %0, %1;" : "=r"(u) : "f"(x));
    return u;
}
__device__ __forceinline__ void mma_tf32(float c[4],
    unsigned a0, unsigned a1, unsigned a2, unsigned a3,
    unsigned b0, unsigned b1)
{
    asm volatile(
        "mma.sync.aligned.m16n8k8.row.col.f32.tf32.tf32.f32 "
        "{%0,%1,%2,%3}, {%4,%5,%6,%7}, {%8,%9}, {%0,%1,%2,%3};\n"
        : "+f"(c[0]), "+f"(c[1]), "+f"(c[2]), "+f"(c[3])
        : "r"(a0), "r"(a1), "r"(a2), "r"(a3), "r"(b0), "r"(b1));
}

// ---------------------------------------------------------------------------
// prep: ||e_k||^2, strict sequential fl(acc + fl(e*e)) (reference order)
// ---------------------------------------------------------------------------
__global__ void enorm_kernel(const float* __restrict__ emb) {
    int k = blockIdx.x * blockDim.x + threadIdx.x;
    if (k < K_TOT) {
        const float* r = emb + (size_t)k * DDIM;
        float s = 0.f;
        #pragma unroll
        for (int c = 0; c < DDIM; ++c)
            s = __fadd_rn(s, __fmul_rn(r[c], r[c]));
        g_enorm[k] = s;
    }
}

// prep: ||z_n||^2, strict sequential order c=0..63 (reference order)
__global__ __launch_bounds__(256) void znorm_kernel(const float* __restrict__ z) {
    __shared__ float zs[DDIM * 64];
    const int tid = threadIdx.x;
    const int n0  = blockIdx.x * 64;
    const int zbase = (n0 >> 12) * 262144 + (n0 & 4095);
    for (int r = tid; r < DDIM * 64; r += 256)
        zs[r] = z[zbase + (r >> 6) * 4096 + (r & 63)];
    __syncthreads();
    if (tid < 64) {
        float s = 0.f;
        #pragma unroll
        for (int c = 0; c < DDIM; ++c) {
            float v = zs[c * 64 + tid];
            s = __fadd_rn(s, __fmul_rn(v, v));
        }
        g_znorm[n0 + tid] = s;
    }
}

// ---------------------------------------------------------------------------
// Pass A: TF32 tensor-core distance, per-(row, 64k-chunk) min
// grid (256, 4): blockIdx.x -> 128-row tile, blockIdx.y -> k range of 2048
// 256 threads = 8 warps, warp w owns rows [16w, 16w+16)
// smem: zs_perm (A frags, 32KB) + es_perm (B frags, 16KB) + en_s (256B)
// ---------------------------------------------------------------------------
extern __shared__ float s_dyn[];

__global__ __launch_bounds__(256) void passA_kernel(
    const float* __restrict__ z, const float* __restrict__ emb)
{
    float* zs_perm = s_dyn;               // [w][s][lane][4]  8192 floats
    float* es_perm = s_dyn + 8192;        // [s][nt][lane][2] 4096 floats
    float* en_s    = s_dyn + 8192 + 4096; // [64]

    const int tid  = threadIdx.x;
    const int lane = tid & 31;
    const int w    = tid >> 5;
    const int n0   = blockIdx.x * M_CTA;
    const int kyb  = blockIdx.y * CHUNKS_PER_CTA;   // chunk index base
    const int zbase = (n0 >> 12) * 262144 + (n0 & 4095);

    // --- stage z tile as A fragments (tf32), coalesced global reads ---
    #pragma unroll
    for (int i = 0; i < 32; ++i) {
        int f = tid + 256 * i;            // 8192 elements
        int col = f >> 7;                 // d  0..63
        int row = f & 127;                // n-local
        unsigned v = tf32u(z[zbase + col * 4096 + row]);
        int ww = row >> 4, r16 = row & 15;
        int g = r16 & 7, hi = r16 >> 3;
        int s = col >> 3, tg = col & 3, half = (col >> 2) & 1;
        int slot = hi + 2 * half;
        int ln = 4 * g + tg;
        ((unsigned*)zs_perm)[((ww * 8 + s) * 32 + ln) * 4 + slot] = v;
    }

    const int g  = lane >> 2;
    const int tg = lane & 3;
    const int row0 = n0 + 16 * w + g;
    const float zn0 = g_znorm[row0];
    const float zn1 = g_znorm[row0 + 8];

    for (int cl = 0; cl < CHUNKS_PER_CTA; ++cl) {
        const int chunkIdx = kyb + cl;
        const int k0 = chunkIdx * CHUNK_K;
        __syncthreads();   // protect previous epilogue's en_s reads

        // --- stage e chunk as B fragments (tf32), float4 global reads ---
        const float4* e4 = (const float4*)(emb + (size_t)k0 * DDIM);
        #pragma unroll
        for (int i = 0; i < 4; ++i) {
            int q = tid + 256 * i;        // 1024 float4
            int kk = q >> 4, d4 = q & 15;
            float4 v = e4[kk * 16 + d4];
            float vv[4] = {v.x, v.y, v.z, v.w};
            int nt = kk >> 3, gc = kk & 7;
            #pragma unroll
            for (int j = 0; j < 4; ++j) {
                int d = 4 * d4 + j;
                int s = d >> 3, dt = d & 3, slot = (d >> 2) & 1;
                int ln = 4 * gc + dt;
                ((unsigned*)es_perm)[((s * 8 + nt) * 32 + ln) * 2 + slot] = tf32u(vv[j]);
            }
        }
        if (tid < 64) en_s[tid] = g_enorm[k0 + tid];
        __syncthreads();

        // --- MMA: (16 rows) x (64 k) x (64 d) per warp ---
        float c[8][4];
        #pragma unroll
        for (int nt = 0; nt < 8; ++nt)
            #pragma unroll
            for (int q = 0; q < 4; ++q) c[nt][q] = 0.f;

        #pragma unroll
        for (int s = 0; s < 8; ++s) {
            uint4 A = *(const uint4*)&((unsigned*)zs_perm)[((w * 8 + s) * 32 + lane) * 4];
            #pragma unroll
            for (int nt = 0; nt < 8; ++nt) {
                uint2 B = *(const uint2*)&((unsigned*)es_perm)[((s * 8 + nt) * 32 + lane) * 2];
                mma_tf32(c[nt], A.x, A.y, A.z, A.w, B.x, B.y);
            }
        }

        // --- epilogue: d = zn + en - 2*dot, min over the 64 k of this chunk ---
        float m0 = 1e30f, m1 = 1e30f;
        #pragma unroll
        for (int nt = 0; nt < 8; ++nt) {
            int kc = 8 * nt + 2 * tg;
            float e0 = en_s[kc], e1 = en_s[kc + 1];
            m0 = fminf(m0, fminf((zn0 + e0) - 2.f * c[nt][0],
                                 (zn0 + e1) - 2.f * c[nt][1]));
            m1 = fminf(m1, fminf((zn1 + e0) - 2.f * c[nt][2],
                                 (zn1 + e1) - 2.f * c[nt][3]));
        }
        m0 = fminf(m0, __shfl_xor_sync(0xffffffffu, m0, 1));
        m0 = fminf(m0, __shfl_xor_sync(0xffffffffu, m0, 2));
        m1 = fminf(m1, __shfl_xor_sync(0xffffffffu, m1, 1));
        m1 = fminf(m1, __shfl_xor_sync(0xffffffffu, m1, 2));
        if (tg == 0) {
            g_chunkmin[(size_t)row0 * NCHUNKS + chunkIdx] = m0;
            g_chunkmin[(size_t)(row0 + 8) * NCHUNKS + chunkIdx] = m1;
        }
    }
}

// ---------------------------------------------------------------------------
// rowmin + winner init: one warp per row
// ---------------------------------------------------------------------------
__global__ __launch_bounds__(256) void rowmin_kernel() {
    const int warp = (blockIdx.x * 256 + threadIdx.x) >> 5;
    const int lane = threadIdx.x & 31;
    if (warp >= N_TOT) return;
    const float* cm = g_chunkmin + (size_t)warp * NCHUNKS;
    float m = 1e30f;
    #pragma unroll
    for (int j = 0; j < 4; ++j) m = fminf(m, cm[lane + 32 * j]);
    #pragma unroll
    for (int o = 16; o > 0; o >>= 1)
        m = fminf(m, __shfl_xor_sync(0xffffffffu, m, o));
    if (lane == 0) { g_rowmin[warp] = m; g_win[warp] = ~0ull; }
}

// ---------------------------------------------------------------------------
// Pass B: exact rescore of surviving chunks (bit-exact reference chain),
// winner via atomicMin on (d_bits<<32 | k)  -> min d, ties -> lowest k
// ---------------------------------------------------------------------------
__global__ __launch_bounds__(256) void passB_kernel(
    const float* __restrict__ z, const float* __restrict__ emb)
{
    const int warp = (blockIdx.x * 256 + threadIdx.x) >> 5;
    const int lane = threadIdx.x & 31;
    if (warp >= N_TOT) return;
    const int row = warp;
    const float thresh = g_rowmin[row] + EPS;
    const float zn = g_znorm[row];
    const int zb = (row >> 12) * 262144 + (row & 4095);

    // z row into 2 regs/lane (d = lane, lane+32), broadcast via shfl
    float zr0 = z[zb + lane * 4096];
    float zr1 = z[zb + (lane + 32) * 4096];

    const float* cm = g_chunkmin + (size_t)row * NCHUNKS;
    #pragma unroll
    for (int j = 0; j < 4; ++j) {
        float v = cm[lane + 32 * j];
        unsigned mask = __ballot_sync(0xffffffffu, v <= thresh);
        while (mask) {
            int b = __ffs(mask) - 1;
            mask &= mask - 1;
            int chunk = b + 32 * j;
            int k0 = chunk * CHUNK_K;
            // each lane rescored 2 codes: k0+lane, k0+lane+32
            #pragma unroll
            for (int h = 0; h < 2; ++h) {
                int k = k0 + lane + 32 * h;
                const float4* er = (const float4*)(emb + (size_t)k * DDIM);
                float s = 0.f;
                #pragma unroll
                for (int d4 = 0; d4 < 16; ++d4) {
                    float4 e = er[d4];
                    int dbase = 4 * d4;
                    float za = __shfl_sync(0xffffffffu, (dbase & 32) ? zr1 : zr0, dbase & 31);
                    float zbv = __shfl_sync(0xffffffffu, ((dbase+1) & 32) ? zr1 : zr0, (dbase+1) & 31);
                    float zc = __shfl_sync(0xffffffffu, ((dbase+2) & 32) ? zr1 : zr0, (dbase+2) & 31);
                    float zd = __shfl_sync(0xffffffffu, ((dbase+3) & 32) ? zr1 : zr0, (dbase+3) & 31);
                    s = __fmaf_rn(za, e.x, s);
                    s = __fmaf_rn(zbv, e.y, s);
                    s = __fmaf_rn(zc, e.z, s);
                    s = __fmaf_rn(zd, e.w, s);
                }
                float d = __fsub_rn(__fadd_rn(zn, g_enorm[k]), __fmul_rn(2.f, s));
                ull key = ((ull)__float_as_uint(d) << 32) | (unsigned)k;
                atomicMin(&g_win[row], key);
            }
        }
    }
}

// ---------------------------------------------------------------------------
// gather: straight-through z_q = fl(z + fl(zq - z)), loss partials, indices
// ---------------------------------------------------------------------------
__global__ __launch_bounds__(256) void gather_kernel(
    const float* __restrict__ z, const float* __restrict__ emb,
    float* __restrict__ out, int out_size)
{
    const int n = blockIdx.x * 256 + threadIdx.x;
    const int idx = (int)(g_win[n] & 0xFFFFFFFFull);
    const int obase = (n >> 12) * 262144 + (n & 4095);

    const float4* er = (const float4*)(emb + (size_t)idx * DDIM);
    float acc = 0.f;
    #pragma unroll
    for (int i = 0; i < DDIM / 4; ++i) {
        float4 e4 = er[i];
        float ev[4] = {e4.x, e4.y, e4.z, e4.w};
        #pragma unroll
        for (int c = 0; c < 4; ++c) {
            int d = 4 * i + c;
            float zv = z[obase + d * 4096];
            float df = __fsub_rn(ev[c], zv);
            out[obase + d * 4096] = __fadd_rn(zv, df);
            acc = fmaf(df, df, acc);
        }
    }
    if (out_size >= ZQ_ELEMS + 1 + N_TOT)
        out[ZQ_ELEMS + 1 + n] = (float)idx;

    __shared__ float red[256];
    red[threadIdx.x] = acc;
    __syncthreads();
    #pragma unroll
    for (int s = 128; s > 0; s >>= 1) {
        if (threadIdx.x < s) red[threadIdx.x] += red[threadIdx.x + s];
        __syncthreads();
    }
    if (threadIdx.x == 0) g_partial[blockIdx.x] = red[0];
}

__global__ void loss_kernel(float* __restrict__ out, int out_size) {
    __shared__ float red[128];
    red[threadIdx.x] = g_partial[threadIdx.x];
    __syncthreads();
    #pragma unroll
    for (int s = 64; s > 0; s >>= 1) {
        if (threadIdx.x < s) red[threadIdx.x] += red[threadIdx.x + s];
        __syncthreads();
    }
    if (threadIdx.x == 0 && out_size >= ZQ_ELEMS + 1) {
        float m = red[0] / (float)ZQ_ELEMS;
        out[ZQ_ELEMS] = __fadd_rn(m, __fmul_rn(0.25f, m));
    }
}

// ---------------------------------------------------------------------------
extern "C" void kernel_launch(void* const* d_in, const int* in_sizes, int n_in,
                              void* d_out, int out_size) {
    const float* z   = (const float*)d_in[0];
    const float* emb = (const float*)d_in[1];
    float* out = (float*)d_out;

    static int smem_set = 0;
    const int SMEM_A = (8192 + 4096 + 64) * 4;   // 49408 B
    if (!smem_set) {
        cudaFuncSetAttribute(passA_kernel,
            cudaFuncAttributeMaxDynamicSharedMemorySize, SMEM_A);
        smem_set = 1;
    }

    enorm_kernel<<<K_TOT / 256, 256>>>(emb);
    znorm_kernel<<<N_TOT / 64, 256>>>(z);
    passA_kernel<<<dim3(N_TOT / M_CTA, KSPLIT), 256, SMEM_A>>>(z, emb);
    rowmin_kernel<<<N_TOT / 8, 256>>>();
    passB_kernel<<<N_TOT / 8, 256>>>(z, emb);
    gather_kernel<<<N_TOT / 256, 256>>>(z, emb, out, out_size);
    loss_kernel<<<1, 128>>>(out, out_size);
}

// round 6
// speedup vs baseline: 2.3477x; 2.1473x over previous
#include <cuda_runtime.h>
#include <cuda_bf16.h>
#include <cstdint>

#define N_TOT 32768
#define K_TOT 8192
#define DDIM  64
#define ZQ_ELEMS 2097152
#define M_CTA 128
#define NB    64                  // codes per tile (= one chunk)
#define NTILES (K_TOT / NB)       // 128
#define NCHUNKS (K_TOT / 64)      // 128
#define EPS_DOT 6e-5f

typedef unsigned long long ull;

// device scratch (no cudaMalloc allowed)
__device__ float g_enorm[K_TOT];
__device__ float g_znorm[N_TOT];
__device__ __align__(16) __nv_bfloat16 g_ebf16[K_TOT * DDIM];  // 1MB, swizzle-ready
__device__ float g_chunkmax[N_TOT * NCHUNKS];                  // 16MB
__device__ ull   g_win[N_TOT];
__device__ float g_partial[128];

// ---------------- helpers ----------------
__device__ __forceinline__ uint32_t smem_u32(const void* p) {
    uint32_t a;
    asm("{ .reg .u64 t; cvta.to.shared.u64 t, %1; cvt.u32.u64 %0, t; }"
        : "=r"(a) : "l"(p));
    return a;
}
__device__ __forceinline__ unsigned packbf(float lo, float hi) {
    __nv_bfloat162 t = __floats2bfloat162_rn(lo, hi);   // .x = lo (low 16 bits)
    return *reinterpret_cast<unsigned*>(&t);
}
__device__ __forceinline__ void mma16816(float c[4], const unsigned a[4],
                                         unsigned b0, unsigned b1) {
    asm volatile(
        "mma.sync.aligned.m16n8k16.row.col.f32.bf16.bf16.f32 "
        "{%0,%1,%2,%3}, {%4,%5,%6,%7}, {%8,%9}, {%0,%1,%2,%3};\n"
        : "+f"(c[0]), "+f"(c[1]), "+f"(c[2]), "+f"(c[3])
        : "r"(a[0]), "r"(a[1]), "r"(a[2]), "r"(a[3]), "r"(b0), "r"(b1));
}

// ---------------------------------------------------------------------------
// prep: ||e||^2 exact (reference order) + bf16 copy of embedding
// ---------------------------------------------------------------------------
__global__ void prep_kernel(const float* __restrict__ emb) {
    int k = blockIdx.x * blockDim.x + threadIdx.x;
    if (k < K_TOT) {
        const float* r = emb + (size_t)k * DDIM;
        __nv_bfloat16* o = g_ebf16 + (size_t)k * DDIM;
        float s = 0.f;
        #pragma unroll
        for (int c = 0; c < DDIM; ++c) {
            float v = r[c];
            s = __fadd_rn(s, __fmul_rn(v, v));
            o[c] = __float2bfloat16(v);
        }
        g_enorm[k] = s;
    }
}

// prep: ||z||^2 exact, strict sequential order c = 0..63
__global__ __launch_bounds__(256) void znorm_kernel(const float* __restrict__ z) {
    __shared__ float zs[DDIM * 64];
    const int tid = threadIdx.x;
    const int n0  = blockIdx.x * 64;
    const int zbase = (n0 >> 12) * 262144 + (n0 & 4095);
    for (int r = tid; r < DDIM * 64; r += 256)
        zs[r] = z[zbase + (r >> 6) * 4096 + (r & 63)];
    __syncthreads();
    if (tid < 64) {
        float s = 0.f;
        #pragma unroll
        for (int c = 0; c < DDIM; ++c) {
            float v = zs[c * 64 + tid];
            s = __fadd_rn(s, __fmul_rn(v, v));
        }
        g_znorm[n0 + tid] = s;
    }
}

// ---------------------------------------------------------------------------
// Pass A: bf16 mma.m16n8k16 dot GEMM + per-64-chunk max
// grid = 256 CTAs (128 rows each) x 256 threads (8 warps x 16 rows)
// smem (32KB union): phase 1 = z transpose staging f32 [64][128];
//                    phase 2 = two 8KB B tile buffers (64 codes x 128B, XOR-swz)
// A fragments live in registers for the whole kernel.
// ---------------------------------------------------------------------------
__global__ __launch_bounds__(256) void passA_kernel(const float* __restrict__ z) {
    __shared__ __align__(16) char smem[32768];
    float* zs = (float*)smem;

    const int tid  = threadIdx.x;
    const int lane = tid & 31;
    const int w    = tid >> 5;
    const int n0   = blockIdx.x * M_CTA;
    const int zbase = (n0 >> 12) * 262144 + (n0 & 4095);

    // ---- phase 1: stage z transposed [d][r] (coalesced), build A frags ----
    #pragma unroll
    for (int i = 0; i < 32; ++i) {
        int f = tid + 256 * i;
        int d = f >> 7, r = f & 127;
        zs[d * 128 + r] = z[zbase + d * 4096 + r];
    }
    __syncthreads();

    const int g  = lane >> 2;          // 0..7
    const int c2 = (lane & 3) * 2;     // k-pair base
    const int rl = 16 * w + g;         // this lane's base row (local)

    unsigned a[4][4];                  // [kstep][frag]
    #pragma unroll
    for (int s = 0; s < 4; ++s) {
        int k0 = 16 * s + c2;
        a[s][0] = packbf(zs[k0 * 128 + rl],           zs[(k0 + 1) * 128 + rl]);
        a[s][1] = packbf(zs[k0 * 128 + rl + 8],       zs[(k0 + 1) * 128 + rl + 8]);
        a[s][2] = packbf(zs[(k0 + 8) * 128 + rl],     zs[(k0 + 9) * 128 + rl]);
        a[s][3] = packbf(zs[(k0 + 8) * 128 + rl + 8], zs[(k0 + 9) * 128 + rl + 8]);
    }
    __syncthreads();   // zs memory now reused for B buffers

    const uint32_t bbase = smem_u32(smem);
    uint4* bufs = (uint4*)smem;        // 2 x 512 uint4 (8KB each)

    // stage tile 0 into buffer 0 (XOR swizzle on 16B units within a code row)
    {
        const uint4* src = (const uint4*)g_ebf16;
        #pragma unroll
        for (int i = 0; i < 2; ++i) {
            int q = tid + 256 * i;               // 0..511
            int code = q >> 3, j = q & 7;
            bufs[code * 8 + (j ^ (code & 7))] = src[q];
        }
    }
    __syncthreads();

    const int row0 = n0 + rl;          // global row for m0 (m1 = +8)
    float* cm0 = g_chunkmax + (size_t)row0 * NCHUNKS;
    float* cm1 = g_chunkmax + (size_t)(row0 + 8) * NCHUNKS;

    const int bcode = lane & 7;                 // ldmatrix row provider
    const int bhalf = (lane >> 3) & 1;          // k half (0: k0-7, 1: k8-15)

    for (int t = 0; t < NTILES; ++t) {
        const uint32_t cur = bbase + (t & 1) * 8192;

        // stage next tile into the other buffer (overlaps compute)
        if (t + 1 < NTILES) {
            const uint4* src = (const uint4*)(g_ebf16 + (size_t)(t + 1) * NB * DDIM);
            uint4* dst = bufs + ((t + 1) & 1) * 512;
            #pragma unroll
            for (int i = 0; i < 2; ++i) {
                int q = tid + 256 * i;
                int code = q >> 3, j = q & 7;
                dst[code * 8 + (j ^ (code & 7))] = src[q];
            }
        }

        // compute: 16 rows x 64 codes x 64 dims per warp
        float cf[8][4];
        #pragma unroll
        for (int nt = 0; nt < 8; ++nt) {
            cf[nt][0] = cf[nt][1] = cf[nt][2] = cf[nt][3] = 0.f;
            #pragma unroll
            for (int s = 0; s < 4; ++s) {
                int code = 8 * nt + bcode;
                int j = 2 * s + bhalf;
                uint32_t addr = cur + code * 128 + (j ^ (code & 7)) * 16;
                unsigned b0, b1;
                asm volatile("ldmatrix.sync.aligned.m8n8.x2.shared.b16 {%0,%1}, [%2];"
                             : "=r"(b0), "=r"(b1) : "r"(addr));
                mma16816(cf[nt], a[s], b0, b1);
            }
        }

        // epilogue: max over the 64 codes of this tile
        float m0 = cf[0][0], m1 = cf[0][2];
        m0 = fmaxf(m0, cf[0][1]); m1 = fmaxf(m1, cf[0][3]);
        #pragma unroll
        for (int nt = 1; nt < 8; ++nt) {
            m0 = fmaxf(m0, fmaxf(cf[nt][0], cf[nt][1]));
            m1 = fmaxf(m1, fmaxf(cf[nt][2], cf[nt][3]));
        }
        m0 = fmaxf(m0, __shfl_xor_sync(~0u, m0, 1));
        m0 = fmaxf(m0, __shfl_xor_sync(~0u, m0, 2));
        m1 = fmaxf(m1, __shfl_xor_sync(~0u, m1, 1));
        m1 = fmaxf(m1, __shfl_xor_sync(~0u, m1, 2));
        if ((lane & 3) == 0) { cm0[t] = m0; cm1[t] = m1; }

        __syncthreads();   // staged buffer ready / old buffer reads done
    }
}

// ---------------------------------------------------------------------------
// Pass B: fused rowmax + exact rescore of surviving chunks (bit-exact chain),
// warp-local key-min (d_bits<<32 | k) -> min d, ties -> lowest k. One warp/row.
// ---------------------------------------------------------------------------
__global__ __launch_bounds__(256) void passB_kernel(
    const float* __restrict__ z, const float* __restrict__ emb)
{
    const int warp = (blockIdx.x * 256 + threadIdx.x) >> 5;
    const int lane = threadIdx.x & 31;
    if (warp >= N_TOT) return;
    const int row = warp;
    const float zn = g_znorm[row];
    const int zb = (row >> 12) * 262144 + (row & 4095);

    const float* cm = g_chunkmax + (size_t)row * NCHUNKS;
    float v4[4];
    float m = -1e30f;
    #pragma unroll
    for (int j = 0; j < 4; ++j) { v4[j] = cm[lane + 32 * j]; m = fmaxf(m, v4[j]); }
    #pragma unroll
    for (int o = 16; o > 0; o >>= 1) m = fmaxf(m, __shfl_xor_sync(~0u, m, o));
    const float thresh = m - EPS_DOT;

    // z row: d = lane and lane+32, broadcast via shfl
    const float zr0 = z[zb + lane * 4096];
    const float zr1 = z[zb + (lane + 32) * 4096];

    ull best = ~0ull;
    #pragma unroll
    for (int j = 0; j < 4; ++j) {
        unsigned mask = __ballot_sync(~0u, v4[j] >= thresh);
        while (mask) {
            int b = __ffs(mask) - 1;
            mask &= mask - 1;
            int k0 = (b + 32 * j) * 64;
            #pragma unroll
            for (int h = 0; h < 2; ++h) {
                int k = k0 + lane + 32 * h;
                const float4* er = (const float4*)(emb + (size_t)k * DDIM);
                float s = 0.f;
                #pragma unroll
                for (int d4 = 0; d4 < 16; ++d4) {
                    float4 e = er[d4];
                    int dbase = 4 * d4;
                    float za  = __shfl_sync(~0u, (dbase & 32) ? zr1 : zr0, dbase & 31);
                    float zbv = __shfl_sync(~0u, ((dbase + 1) & 32) ? zr1 : zr0, (dbase + 1) & 31);
                    float zc  = __shfl_sync(~0u, ((dbase + 2) & 32) ? zr1 : zr0, (dbase + 2) & 31);
                    float zd  = __shfl_sync(~0u, ((dbase + 3) & 32) ? zr1 : zr0, (dbase + 3) & 31);
                    s = __fmaf_rn(za, e.x, s);
                    s = __fmaf_rn(zbv, e.y, s);
                    s = __fmaf_rn(zc, e.z, s);
                    s = __fmaf_rn(zd, e.w, s);
                }
                float d = __fsub_rn(__fadd_rn(zn, g_enorm[k]), __fmul_rn(2.f, s));
                ull key = ((ull)__float_as_uint(d) << 32) | (unsigned)k;
                if (key < best) best = key;
            }
        }
    }
    #pragma unroll
    for (int o = 16; o > 0; o >>= 1) {
        ull o2 = __shfl_xor_sync(~0u, best, o);
        if (o2 < best) best = o2;
    }
    if (lane == 0) g_win[row] = best;
}

// ---------------------------------------------------------------------------
// gather: z_q = fl(z + fl(zq - z)) (exact reference ops), loss partials, idx
// ---------------------------------------------------------------------------
__global__ __launch_bounds__(256) void gather_kernel(
    const float* __restrict__ z, const float* __restrict__ emb,
    float* __restrict__ out, int out_size)
{
    const int n = blockIdx.x * 256 + threadIdx.x;
    const int idx = (int)(g_win[n] & 0xFFFFFFFFull);
    const int obase = (n >> 12) * 262144 + (n & 4095);

    const float4* er = (const float4*)(emb + (size_t)idx * DDIM);
    float acc = 0.f;
    #pragma unroll
    for (int i = 0; i < DDIM / 4; ++i) {
        float4 e4 = er[i];
        float ev[4] = {e4.x, e4.y, e4.z, e4.w};
        #pragma unroll
        for (int c = 0; c < 4; ++c) {
            int d = 4 * i + c;
            float zv = z[obase + d * 4096];
            float df = __fsub_rn(ev[c], zv);
            out[obase + d * 4096] = __fadd_rn(zv, df);
            acc = fmaf(df, df, acc);
        }
    }
    if (out_size >= ZQ_ELEMS + 1 + N_TOT)
        out[ZQ_ELEMS + 1 + n] = (float)idx;

    __shared__ float red[256];
    red[threadIdx.x] = acc;
    __syncthreads();
    #pragma unroll
    for (int s = 128; s > 0; s >>= 1) {
        if (threadIdx.x < s) red[threadIdx.x] += red[threadIdx.x + s];
        __syncthreads();
    }
    if (threadIdx.x == 0) g_partial[blockIdx.x] = red[0];
}

__global__ void loss_kernel(float* __restrict__ out, int out_size) {
    __shared__ float red[128];
    red[threadIdx.x] = g_partial[threadIdx.x];
    __syncthreads();
    #pragma unroll
    for (int s = 64; s > 0; s >>= 1) {
        if (threadIdx.x < s) red[threadIdx.x] += red[threadIdx.x + s];
        __syncthreads();
    }
    if (threadIdx.x == 0 && out_size >= ZQ_ELEMS + 1) {
        float m = red[0] / (float)ZQ_ELEMS;
        out[ZQ_ELEMS] = __fadd_rn(m, __fmul_rn(0.25f, m));
    }
}

// ---------------------------------------------------------------------------
extern "C" void kernel_launch(void* const* d_in, const int* in_sizes, int n_in,
                              void* d_out, int out_size) {
    const float* z   = (const float*)d_in[0];
    const float* emb = (const float*)d_in[1];
    float* out = (float*)d_out;

    prep_kernel<<<K_TOT / 256, 256>>>(emb);
    znorm_kernel<<<N_TOT / 64, 256>>>(z);
    passA_kernel<<<N_TOT / M_CTA, 256>>>(z);
    passB_kernel<<<N_TOT / 8, 256>>>(z, emb);
    gather_kernel<<<N_TOT / 256, 256>>>(z, emb, out, out_size);
    loss_kernel<<<1, 128>>>(out, out_size);
}

// round 7
// speedup vs baseline: 2.5038x; 1.0665x over previous
#include <cuda_runtime.h>
#include <cuda_bf16.h>
#include <cstdint>

#define N_TOT 32768
#define K_TOT 8192
#define DDIM  64
#define ZQ_ELEMS 2097152
#define M_CTA 128
#define NB    64                  // codes per tile
#define NTILES (K_TOT / NB)       // 128
#define NGROUPS (K_TOT / 16)      // 512 (16-code filter groups)
#define EPS_DOT 6e-5f

typedef unsigned long long ull;

// device scratch (no cudaMalloc allowed)
__device__ float g_enorm[K_TOT];
__device__ float g_znorm[N_TOT];
__device__ __align__(16) __nv_bfloat16 g_ebf16[K_TOT * DDIM];  // 1MB
__device__ float g_groupmax[(size_t)N_TOT * NGROUPS];          // 64MB
__device__ ull   g_win[N_TOT];
__device__ float g_partial[128];

// ---------------- helpers ----------------
__device__ __forceinline__ uint32_t smem_u32(const void* p) {
    uint32_t a;
    asm("{ .reg .u64 t; cvta.to.shared.u64 t, %1; cvt.u32.u64 %0, t; }"
        : "=r"(a) : "l"(p));
    return a;
}
__device__ __forceinline__ unsigned packbf(float lo, float hi) {
    __nv_bfloat162 t = __floats2bfloat162_rn(lo, hi);
    return *reinterpret_cast<unsigned*>(&t);
}
__device__ __forceinline__ void mma16816(float c[4], const unsigned a[4],
                                         unsigned b0, unsigned b1) {
    asm volatile(
        "mma.sync.aligned.m16n8k16.row.col.f32.bf16.bf16.f32 "
        "{%0,%1,%2,%3}, {%4,%5,%6,%7}, {%8,%9}, {%0,%1,%2,%3};\n"
        : "+f"(c[0]), "+f"(c[1]), "+f"(c[2]), "+f"(c[3])
        : "r"(a[0]), "r"(a[1]), "r"(a[2]), "r"(a[3]), "r"(b0), "r"(b1));
}

// ---------------------------------------------------------------------------
// prep: ||e||^2 exact (reference order) + bf16 copy of embedding
// ---------------------------------------------------------------------------
__global__ void prep_kernel(const float* __restrict__ emb) {
    int k = blockIdx.x * blockDim.x + threadIdx.x;
    if (k < K_TOT) {
        const float* r = emb + (size_t)k * DDIM;
        __nv_bfloat16* o = g_ebf16 + (size_t)k * DDIM;
        float s = 0.f;
        #pragma unroll
        for (int c = 0; c < DDIM; ++c) {
            float v = r[c];
            s = __fadd_rn(s, __fmul_rn(v, v));
            o[c] = __float2bfloat16(v);
        }
        g_enorm[k] = s;
    }
}

// prep: ||z||^2 exact, strict sequential order c = 0..63
__global__ __launch_bounds__(256) void znorm_kernel(const float* __restrict__ z) {
    __shared__ float zs[DDIM * 64];
    const int tid = threadIdx.x;
    const int n0  = blockIdx.x * 64;
    const int zbase = (n0 >> 12) * 262144 + (n0 & 4095);
    for (int r = tid; r < DDIM * 64; r += 256)
        zs[r] = z[zbase + (r >> 6) * 4096 + (r & 63)];
    __syncthreads();
    if (tid < 64) {
        float s = 0.f;
        #pragma unroll
        for (int c = 0; c < DDIM; ++c) {
            float v = zs[c * 64 + tid];
            s = __fadd_rn(s, __fmul_rn(v, v));
        }
        g_znorm[n0 + tid] = s;
    }
}

// ---------------------------------------------------------------------------
// Pass A: bf16 mma.m16n8k16 dot GEMM + per-16-code-group max
// grid = 256 CTAs (128 rows) x 256 threads (8 warps x 16 rows)
// ---------------------------------------------------------------------------
__global__ __launch_bounds__(256) void passA_kernel(const float* __restrict__ z) {
    __shared__ __align__(16) char smem[32768];
    float* zs = (float*)smem;

    const int tid  = threadIdx.x;
    const int lane = tid & 31;
    const int w    = tid >> 5;
    const int n0   = blockIdx.x * M_CTA;
    const int zbase = (n0 >> 12) * 262144 + (n0 & 4095);

    // ---- phase 1: stage z transposed [d][r] (coalesced), build A frags ----
    #pragma unroll
    for (int i = 0; i < 32; ++i) {
        int f = tid + 256 * i;
        int d = f >> 7, r = f & 127;
        zs[d * 128 + r] = z[zbase + d * 4096 + r];
    }
    __syncthreads();

    const int g  = lane >> 2;
    const int c2 = (lane & 3) * 2;
    const int rl = 16 * w + g;

    unsigned a[4][4];
    #pragma unroll
    for (int s = 0; s < 4; ++s) {
        int k0 = 16 * s + c2;
        a[s][0] = packbf(zs[k0 * 128 + rl],           zs[(k0 + 1) * 128 + rl]);
        a[s][1] = packbf(zs[k0 * 128 + rl + 8],       zs[(k0 + 1) * 128 + rl + 8]);
        a[s][2] = packbf(zs[(k0 + 8) * 128 + rl],     zs[(k0 + 9) * 128 + rl]);
        a[s][3] = packbf(zs[(k0 + 8) * 128 + rl + 8], zs[(k0 + 9) * 128 + rl + 8]);
    }
    __syncthreads();

    const uint32_t bbase = smem_u32(smem);
    uint4* bufs = (uint4*)smem;

    // stage tile 0 into buffer 0
    {
        const uint4* src = (const uint4*)g_ebf16;
        #pragma unroll
        for (int i = 0; i < 2; ++i) {
            int q = tid + 256 * i;
            int code = q >> 3, j = q & 7;
            bufs[code * 8 + (j ^ (code & 7))] = src[q];
        }
    }
    __syncthreads();

    const int row0 = n0 + rl;
    float* gm0 = g_groupmax + (size_t)row0 * NGROUPS;
    float* gm1 = g_groupmax + (size_t)(row0 + 8) * NGROUPS;

    const int bcode = lane & 7;
    const int bhalf = (lane >> 3) & 1;

    for (int t = 0; t < NTILES; ++t) {
        const uint32_t cur = bbase + (t & 1) * 8192;

        if (t + 1 < NTILES) {
            const uint4* src = (const uint4*)(g_ebf16 + (size_t)(t + 1) * NB * DDIM);
            uint4* dst = bufs + ((t + 1) & 1) * 512;
            #pragma unroll
            for (int i = 0; i < 2; ++i) {
                int q = tid + 256 * i;
                int code = q >> 3, j = q & 7;
                dst[code * 8 + (j ^ (code & 7))] = src[q];
            }
        }

        float cf[8][4];
        #pragma unroll
        for (int nt = 0; nt < 8; ++nt) {
            cf[nt][0] = cf[nt][1] = cf[nt][2] = cf[nt][3] = 0.f;
            #pragma unroll
            for (int s = 0; s < 4; ++s) {
                int code = 8 * nt + bcode;
                int j = 2 * s + bhalf;
                uint32_t addr = cur + code * 128 + (j ^ (code & 7)) * 16;
                unsigned b0, b1;
                asm volatile("ldmatrix.sync.aligned.m8n8.x2.shared.b16 {%0,%1}, [%2];"
                             : "=r"(b0), "=r"(b1) : "r"(addr));
                mma16816(cf[nt], a[s], b0, b1);
            }
        }

        // epilogue: per-16-code-group max (group gr = nt pair {2gr, 2gr+1})
        #pragma unroll
        for (int gr = 0; gr < 4; ++gr) {
            float m0 = fmaxf(fmaxf(cf[2 * gr][0], cf[2 * gr][1]),
                             fmaxf(cf[2 * gr + 1][0], cf[2 * gr + 1][1]));
            float m1 = fmaxf(fmaxf(cf[2 * gr][2], cf[2 * gr][3]),
                             fmaxf(cf[2 * gr + 1][2], cf[2 * gr + 1][3]));
            m0 = fmaxf(m0, __shfl_xor_sync(~0u, m0, 1));
            m0 = fmaxf(m0, __shfl_xor_sync(~0u, m0, 2));
            m1 = fmaxf(m1, __shfl_xor_sync(~0u, m1, 1));
            m1 = fmaxf(m1, __shfl_xor_sync(~0u, m1, 2));
            if ((lane & 3) == 0) {
                gm0[t * 4 + gr] = m0;
                gm1[t * 4 + gr] = m1;
            }
        }

        __syncthreads();
    }
}

// ---------------------------------------------------------------------------
// Pass B: fused rowmax + exact rescore of surviving 16-code groups.
// One warp per row; lane (&15) rescored one code per survivor group.
// Winner key-min (d_bits<<32 | k): min d, ties -> lowest k. Low-reg for occ.
// ---------------------------------------------------------------------------
__global__ __launch_bounds__(256) void passB_kernel(
    const float* __restrict__ z, const float* __restrict__ emb)
{
    const int warp = (blockIdx.x * 256 + threadIdx.x) >> 5;
    const int lane = threadIdx.x & 31;
    if (warp >= N_TOT) return;
    const int row = warp;
    const float zn = g_znorm[row];
    const int zb = (row >> 12) * 262144 + (row & 4095);

    const float* gm = g_groupmax + (size_t)row * NGROUPS;
    float v[16];
    float m = -1e30f;
    #pragma unroll
    for (int j = 0; j < 16; ++j) { v[j] = gm[lane + 32 * j]; m = fmaxf(m, v[j]); }
    #pragma unroll
    for (int o = 16; o > 0; o >>= 1) m = fmaxf(m, __shfl_xor_sync(~0u, m, o));
    const float thresh = m - EPS_DOT;

    // z row: d = lane and lane+32, broadcast via shfl inside survivor loop
    const float zr0 = z[zb + lane * 4096];
    const float zr1 = z[zb + (lane + 32) * 4096];

    ull best = ~0ull;
    #pragma unroll
    for (int j = 0; j < 16; ++j) {
        unsigned mask = __ballot_sync(~0u, v[j] >= thresh);
        while (mask) {
            int b = __ffs(mask) - 1;
            mask &= mask - 1;
            int k = (b + 32 * j) * 16 + (lane & 15);   // lanes 16-31 duplicate
            const float4* er = (const float4*)(emb + (size_t)k * DDIM);
            float s = 0.f;
            #pragma unroll
            for (int d4 = 0; d4 < 16; ++d4) {
                float4 e = er[d4];
                int dbase = 4 * d4;
                float za  = __shfl_sync(~0u, (dbase & 32) ? zr1 : zr0, dbase & 31);
                float zbv = __shfl_sync(~0u, ((dbase + 1) & 32) ? zr1 : zr0, (dbase + 1) & 31);
                float zc  = __shfl_sync(~0u, ((dbase + 2) & 32) ? zr1 : zr0, (dbase + 2) & 31);
                float zd  = __shfl_sync(~0u, ((dbase + 3) & 32) ? zr1 : zr0, (dbase + 3) & 31);
                s = __fmaf_rn(za, e.x, s);
                s = __fmaf_rn(zbv, e.y, s);
                s = __fmaf_rn(zc, e.z, s);
                s = __fmaf_rn(zd, e.w, s);
            }
            float d = __fsub_rn(__fadd_rn(zn, g_enorm[k]), __fmul_rn(2.f, s));
            ull key = ((ull)__float_as_uint(d) << 32) | (unsigned)k;
            if (key < best) best = key;
        }
    }
    #pragma unroll
    for (int o = 16; o > 0; o >>= 1) {
        ull o2 = __shfl_xor_sync(~0u, best, o);
        if (o2 < best) best = o2;
    }
    if (lane == 0) g_win[row] = best;
}

// ---------------------------------------------------------------------------
// gather: z_q = fl(z + fl(zq - z)) (exact reference ops), loss partials, idx
// ---------------------------------------------------------------------------
__global__ __launch_bounds__(256) void gather_kernel(
    const float* __restrict__ z, const float* __restrict__ emb,
    float* __restrict__ out, int out_size)
{
    const int n = blockIdx.x * 256 + threadIdx.x;
    const int idx = (int)(g_win[n] & 0xFFFFFFFFull);
    const int obase = (n >> 12) * 262144 + (n & 4095);

    const float4* er = (const float4*)(emb + (size_t)idx * DDIM);
    float acc = 0.f;
    #pragma unroll
    for (int i = 0; i < DDIM / 4; ++i) {
        float4 e4 = er[i];
        float ev[4] = {e4.x, e4.y, e4.z, e4.w};
        #pragma unroll
        for (int c = 0; c < 4; ++c) {
            int d = 4 * i + c;
            float zv = z[obase + d * 4096];
            float df = __fsub_rn(ev[c], zv);
            out[obase + d * 4096] = __fadd_rn(zv, df);
            acc = fmaf(df, df, acc);
        }
    }
    if (out_size >= ZQ_ELEMS + 1 + N_TOT)
        out[ZQ_ELEMS + 1 + n] = (float)idx;

    __shared__ float red[256];
    red[threadIdx.x] = acc;
    __syncthreads();
    #pragma unroll
    for (int s = 128; s > 0; s >>= 1) {
        if (threadIdx.x < s) red[threadIdx.x] += red[threadIdx.x + s];
        __syncthreads();
    }
    if (threadIdx.x == 0) g_partial[blockIdx.x] = red[0];
}

__global__ void loss_kernel(float* __restrict__ out, int out_size) {
    __shared__ float red[128];
    red[threadIdx.x] = g_partial[threadIdx.x];
    __syncthreads();
    #pragma unroll
    for (int s = 64; s > 0; s >>= 1) {
        if (threadIdx.x < s) red[threadIdx.x] += red[threadIdx.x + s];
        __syncthreads();
    }
    if (threadIdx.x == 0 && out_size >= ZQ_ELEMS + 1) {
        float m = red[0] / (float)ZQ_ELEMS;
        out[ZQ_ELEMS] = __fadd_rn(m, __fmul_rn(0.25f, m));
    }
}

// ---------------------------------------------------------------------------
extern "C" void kernel_launch(void* const* d_in, const int* in_sizes, int n_in,
                              void* d_out, int out_size) {
    const float* z   = (const float*)d_in[0];
    const float* emb = (const float*)d_in[1];
    float* out = (float*)d_out;

    prep_kernel<<<K_TOT / 256, 256>>>(emb);
    znorm_kernel<<<N_TOT / 64, 256>>>(z);
    passA_kernel<<<N_TOT / M_CTA, 256>>>(z);
    passB_kernel<<<N_TOT / 8, 256>>>(z, emb);
    gather_kernel<<<N_TOT / 256, 256>>>(z, emb, out, out_size);
    loss_kernel<<<1, 128>>>(out, out_size);
}